// round 4
// baseline (speedup 1.0000x reference)
#include <cuda_runtime.h>
#include <math.h>

typedef unsigned long long u64;

#define TM  32        // batch rows per CTA
#define NT  256       // threads per CTA
#define PAD 36        // smem row stride in floats (16B-aligned)

// ---- shared memory layout (floats) ----
#define OFF_X1   0                        // [1024][PAD]
#define OFF_X2   (1024*PAD)               // [512][PAD]
#define OFF_X0   (OFF_X2 + 512*PAD)       // [32][PAD]
#define OFF_G1   (OFF_X0 + 32*PAD)
#define OFF_G2   (OFF_G1 + 32)
#define OFF_STAT (OFF_G2 + 32)
#define OFF_MU   (OFF_STAT + 512)
#define OFF_RS   (OFF_MU + 32)
#define OFF_W3   (OFF_RS + 32)
#define SMEM_FLOATS (OFF_W3 + 128)        // 57216 floats = 228864 B

// ---- packed fp32x2 helpers (sm_103a FFMA2 via PTX) ----
__device__ __forceinline__ void fma2(u64 &acc, u64 x, u64 w) {
    asm("fma.rn.f32x2 %0, %1, %2, %0;" : "+l"(acc) : "l"(x), "l"(w));
}
__device__ __forceinline__ u64 pack2(float w) {
    u64 r; asm("mov.b64 %0, {%1, %1};" : "=l"(r) : "f"(w)); return r;
}
__device__ __forceinline__ float2 unpack2(u64 v) {
    float2 f; asm("mov.b64 {%0, %1}, %2;" : "=f"(f.x), "=f"(f.y) : "l"(v)); return f;
}
__device__ __forceinline__ float acc_tanh(float x) {
    float e = expf(2.0f * x);
    return 1.0f - 2.0f / (e + 1.0f);
}

__global__ __launch_bounds__(NT, 1)
void cor_critic_fused(const float* __restrict__ state, const float* __restrict__ action,
                      const float* __restrict__ W1, const float* __restrict__ b1, const float* __restrict__ g1,
                      const float* __restrict__ W2, const float* __restrict__ b2, const float* __restrict__ g2,
                      const float* __restrict__ Wq1, const float* __restrict__ bq1,
                      const float* __restrict__ ln1g, const float* __restrict__ ln1b,
                      const float* __restrict__ Wq2, const float* __restrict__ bq2,
                      const float* __restrict__ ln2g, const float* __restrict__ ln2b,
                      const float* __restrict__ Wq3, const float* __restrict__ bq3,
                      float* __restrict__ out)
{
    extern __shared__ float sm[];
    float* sX1 = sm + OFF_X1;
    float* sX2 = sm + OFF_X2;
    float* sX0 = sm + OFF_X0;

    const int tid  = threadIdx.x;
    const int row0 = blockIdx.x * TM;

    // ---- prologue ----
    if (tid < 32) {
        sm[OFF_G1 + tid] = 1.0f / (1.0f + expf(-__ldg(g1 + tid)));
        sm[OFF_G2 + tid] = 1.0f / (1.0f + expf(-__ldg(g2 + tid)));
    }
    if (tid < 128) sm[OFF_W3 + tid] = __ldg(Wq3 + tid);

    for (int i = tid; i < 32 * TM; i += NT) {
        int r = i >> 5, d = i & 31;
        float v = (d < 24) ? __ldg(state + (size_t)(row0 + r) * 24 + d)
                           : __ldg(action + (size_t)(row0 + r) * 8 + (d - 24));
        sX0[d * PAD + r] = v;
    }
    __syncthreads();

    // ---- Stage 1: X1 = tanh(X0 @ A1 + b1) * sig(g1) ----
    #pragma unroll 1
    for (int p = 0; p < 2; ++p) {
        const int c0 = p * 512 + tid, c1 = c0 + 256;
        const float* pW0 = W1 + (c0 >> 5) * 1024 + (c0 & 31);
        const float* pW1 = W1 + (c1 >> 5) * 1024 + (c1 & 31);
        u64 a0[16], a1[16];
        #pragma unroll
        for (int i = 0; i < 16; ++i) { a0[i] = 0ull; a1[i] = 0ull; }
        #pragma unroll 4
        for (int d = 0; d < 32; ++d) {
            u64 w20 = pack2(__ldg(pW0 + d * 32));
            u64 w21 = pack2(__ldg(pW1 + d * 32));
            const ulonglong2* xr = (const ulonglong2*)(sX0 + d * PAD);
            #pragma unroll
            for (int i = 0; i < 8; ++i) {
                ulonglong2 x = xr[i];
                fma2(a0[2*i], x.x, w20); fma2(a0[2*i+1], x.y, w20);
                fma2(a1[2*i], x.x, w21); fma2(a1[2*i+1], x.y, w21);
            }
        }
        float bb0 = __ldg(b1 + c0), gg0 = sm[OFF_G1 + (c0 >> 5)];
        float bb1 = __ldg(b1 + c1), gg1 = sm[OFF_G1 + (c1 >> 5)];
        float2* o0 = (float2*)(sX1 + c0 * PAD);
        float2* o1 = (float2*)(sX1 + c1 * PAD);
        #pragma unroll
        for (int i = 0; i < 16; ++i) {
            float2 v0 = unpack2(a0[i]), v1 = unpack2(a1[i]);
            o0[i] = make_float2(acc_tanh(v0.x+bb0)*gg0, acc_tanh(v0.y+bb0)*gg0);
            o1[i] = make_float2(acc_tanh(v1.x+bb1)*gg1, acc_tanh(v1.y+bb1)*gg1);
        }
    }
    __syncthreads();

    // ---- Stage 2: X2 = tanh(X1 @ A2 + b2) * sig(g2) ----
    #pragma unroll 1
    for (int p = 0; p < 2; ++p) {
        const int c0 = p * 512 + tid, c1 = c0 + 256;
        const float* pW0 = W2 + (size_t)(c0 >> 5) * 32768 + (c0 & 31);
        const float* pW1 = W2 + (size_t)(c1 >> 5) * 32768 + (c1 & 31);
        u64 a0[16], a1[16];
        #pragma unroll
        for (int i = 0; i < 16; ++i) { a0[i] = 0ull; a1[i] = 0ull; }

        float wa0[4], wa1[4];
        #pragma unroll
        for (int j = 0; j < 4; ++j) { wa0[j] = __ldg(pW0 + j*32); wa1[j] = __ldg(pW1 + j*32); }

        #pragma unroll 1
        for (int db = 0; db < 1024; db += 4) {
            const int dn = (db + 4 < 1024) ? (db + 4) : 0;
            float wn0[4], wn1[4];
            #pragma unroll
            for (int j = 0; j < 4; ++j) { wn0[j] = __ldg(pW0 + (dn+j)*32); wn1[j] = __ldg(pW1 + (dn+j)*32); }
            #pragma unroll
            for (int j = 0; j < 4; ++j) {
                const ulonglong2* xr = (const ulonglong2*)(sX1 + (db + j) * PAD);
                u64 w20 = pack2(wa0[j]), w21 = pack2(wa1[j]);
                #pragma unroll
                for (int i = 0; i < 8; ++i) {
                    ulonglong2 x = xr[i];
                    fma2(a0[2*i], x.x, w20); fma2(a0[2*i+1], x.y, w20);
                    fma2(a1[2*i], x.x, w21); fma2(a1[2*i+1], x.y, w21);
                }
            }
            #pragma unroll
            for (int j = 0; j < 4; ++j) { wa0[j] = wn0[j]; wa1[j] = wn1[j]; }
        }

        float bb0 = __ldg(b2 + c0), gg0 = sm[OFF_G2 + (c0 >> 5)];
        float bb1 = __ldg(b2 + c1), gg1 = sm[OFF_G2 + (c1 >> 5)];
        if (p == 1) __syncthreads();   // X1 reads done before overwrite
        float2* o0 = (p == 0) ? (float2*)(sX2 + c0 * PAD) : (float2*)(sX1 + (c0 - 512) * PAD);
        float2* o1 = (p == 0) ? (float2*)(sX2 + c1 * PAD) : (float2*)(sX1 + (c1 - 512) * PAD);
        #pragma unroll
        for (int i = 0; i < 16; ++i) {
            float2 v0 = unpack2(a0[i]), v1 = unpack2(a1[i]);
            o0[i] = make_float2(acc_tanh(v0.x+bb0)*gg0, acc_tanh(v0.y+bb0)*gg0);
            o1[i] = make_float2(acc_tanh(v1.x+bb1)*gg1, acc_tanh(v1.y+bb1)*gg1);
        }
    }
    __syncthreads();

    // ---- Stage 3: H1pre = X2 @ Wq1. Thread = 2 cols (cc, cc+128) x 16 rows (rh half) ----
    const int rh = tid >> 7;       // 0/1 row half
    const int cc = tid & 127;
    u64 A0[8], A1[8];
    #pragma unroll
    for (int i = 0; i < 8; ++i) { A0[i] = 0ull; A1[i] = 0ull; }
    #pragma unroll 1
    for (int s = 0; s < 2; ++s) {
        const float* xb = (s == 0) ? sX2 : sX1;
        const float* wb = Wq1 + (size_t)(s * 512) * 256;
        float wc0[4], wc1[4];
        #pragma unroll
        for (int j = 0; j < 4; ++j) { wc0[j] = __ldg(wb + j*256 + cc); wc1[j] = __ldg(wb + j*256 + cc + 128); }
        #pragma unroll 1
        for (int nb = 0; nb < 512; nb += 4) {
            int nn = (nb + 4 < 512) ? (nb + 4) : 0;
            float wn0[4], wn1[4];
            #pragma unroll
            for (int j = 0; j < 4; ++j) { wn0[j] = __ldg(wb + (nn+j)*256 + cc); wn1[j] = __ldg(wb + (nn+j)*256 + cc + 128); }
            #pragma unroll
            for (int j = 0; j < 4; ++j) {
                const ulonglong2* xr = (const ulonglong2*)(xb + (nb + j) * PAD + rh * 16);
                u64 w20 = pack2(wc0[j]), w21 = pack2(wc1[j]);
                #pragma unroll
                for (int i = 0; i < 4; ++i) {
                    ulonglong2 x = xr[i];
                    fma2(A0[2*i], x.x, w20); fma2(A0[2*i+1], x.y, w20);
                    fma2(A1[2*i], x.x, w21); fma2(A1[2*i+1], x.y, w21);
                }
            }
            #pragma unroll
            for (int j = 0; j < 4; ++j) { wc0[j] = wn0[j]; wc1[j] = wn1[j]; }
        }
    }
    __syncthreads();               // X2 reads done before H1 overwrites sX2
    {
        float bb0 = __ldg(bq1 + cc), bb1 = __ldg(bq1 + cc + 128);
        float* h0 = sX2 + cc * PAD + rh * 16;
        float* h1 = sX2 + (cc + 128) * PAD + rh * 16;
        #pragma unroll
        for (int i = 0; i < 8; ++i) {
            float2 v0 = unpack2(A0[i]), v1 = unpack2(A1[i]);
            h0[2*i] = v0.x + bb0; h0[2*i+1] = v0.y + bb0;
            h1[2*i] = v1.x + bb1; h1[2*i+1] = v1.y + bb1;
        }
    }
    __syncthreads();

    // ---- LN1 + relu over sH1 = sX2[256][PAD] ----
    {
        int r = tid & 31, seg = tid >> 5;
        float s = 0.f, s2 = 0.f;
        for (int q = seg * 32; q < seg * 32 + 32; ++q) {
            float v = sX2[q * PAD + r]; s += v; s2 += v * v;
        }
        sm[OFF_STAT + seg * 32 + r] = s;
        sm[OFF_STAT + 256 + seg * 32 + r] = s2;
    }
    __syncthreads();
    if (tid < 32) {
        float s = 0.f, s2 = 0.f;
        #pragma unroll
        for (int g = 0; g < 8; ++g) { s += sm[OFF_STAT + g*32 + tid]; s2 += sm[OFF_STAT + 256 + g*32 + tid]; }
        float mu = s * (1.0f / 256.0f);
        float var = s2 * (1.0f / 256.0f) - mu * mu;
        sm[OFF_MU + tid] = mu;
        sm[OFF_RS + tid] = rsqrtf(var + 1e-5f);
    }
    __syncthreads();
    {
        float gq = __ldg(ln1g + tid), bqv = __ldg(ln1b + tid);
        float* h = sX2 + tid * PAD;
        #pragma unroll
        for (int r = 0; r < TM; ++r) {
            float v = (h[r] - sm[OFF_MU + r]) * sm[OFF_RS + r] * gq + bqv;
            h[r] = fmaxf(v, 0.0f);
        }
    }
    __syncthreads();

    // ---- Stage 4: H2pre = H1 @ Wq2. Thread = 2 cols (c4, c4+64) x 8 rows (grp) ----
    float* sH2 = sX2 + 256 * PAD;
    {
        const int grp = tid >> 6;   // 0..3
        const int c4  = tid & 63;
        u64 B0[4], B1[4];
        #pragma unroll
        for (int i = 0; i < 4; ++i) { B0[i] = 0ull; B1[i] = 0ull; }
        const float* wb = Wq2 + c4;
        #pragma unroll 4
        for (int n = 0; n < 256; ++n) {
            u64 w20 = pack2(__ldg(wb + n * 128));
            u64 w21 = pack2(__ldg(wb + n * 128 + 64));
            const ulonglong2* xr = (const ulonglong2*)(sX2 + n * PAD + grp * 8);
            #pragma unroll
            for (int i = 0; i < 2; ++i) {
                ulonglong2 x = xr[i];
                fma2(B0[2*i], x.x, w20); fma2(B0[2*i+1], x.y, w20);
                fma2(B1[2*i], x.x, w21); fma2(B1[2*i+1], x.y, w21);
            }
        }
        float bb0 = __ldg(bq2 + c4), bb1 = __ldg(bq2 + c4 + 64);
        float* h0 = sH2 + c4 * PAD + grp * 8;
        float* h1 = sH2 + (c4 + 64) * PAD + grp * 8;
        #pragma unroll
        for (int i = 0; i < 4; ++i) {
            float2 v0 = unpack2(B0[i]), v1 = unpack2(B1[i]);
            h0[2*i] = v0.x + bb0; h0[2*i+1] = v0.y + bb0;
            h1[2*i] = v1.x + bb1; h1[2*i+1] = v1.y + bb1;
        }
    }
    __syncthreads();

    // ---- LN2 + relu ----
    {
        int r = tid & 31, seg = tid >> 5;
        if (seg < 4) {
            float s = 0.f, s2 = 0.f;
            for (int q = seg * 32; q < seg * 32 + 32; ++q) {
                float v = sH2[q * PAD + r]; s += v; s2 += v * v;
            }
            sm[OFF_STAT + seg * 32 + r] = s;
            sm[OFF_STAT + 256 + seg * 32 + r] = s2;
        }
    }
    __syncthreads();
    if (tid < 32) {
        float s = 0.f, s2 = 0.f;
        #pragma unroll
        for (int g = 0; g < 4; ++g) { s += sm[OFF_STAT + g*32 + tid]; s2 += sm[OFF_STAT + 256 + g*32 + tid]; }
        float mu = s * (1.0f / 128.0f);
        float var = s2 * (1.0f / 128.0f) - mu * mu;
        sm[OFF_MU + tid] = mu;
        sm[OFF_RS + tid] = rsqrtf(var + 1e-5f);
    }
    __syncthreads();
    if (tid < 128) {
        float gq = __ldg(ln2g + tid), bqv = __ldg(ln2b + tid);
        float* h = sH2 + tid * PAD;
        #pragma unroll
        for (int r = 0; r < TM; ++r) {
            float v = (h[r] - sm[OFF_MU + r]) * sm[OFF_RS + r] * gq + bqv;
            h[r] = fmaxf(v, 0.0f);
        }
    }
    __syncthreads();

    // ---- Stage 5: out = H2 @ Wq3 + bq3 ----
    {
        float bq3v = __ldg(bq3);
        int w = tid >> 5, lane = tid & 31;
        #pragma unroll
        for (int rr = 0; rr < 4; ++rr) {
            int r = w * 4 + rr;
            float s = 0.f;
            #pragma unroll
            for (int j = 0; j < 4; ++j) {
                int q = lane + j * 32;
                s += sH2[q * PAD + r] * sm[OFF_W3 + q];
            }
            #pragma unroll
            for (int off = 16; off; off >>= 1) s += __shfl_xor_sync(0xffffffffu, s, off);
            if (lane == 0) out[row0 + r] = s + bq3v;
        }
    }
}

extern "C" void kernel_launch(void* const* d_in, const int* in_sizes, int n_in,
                              void* d_out, int out_size) {
    const float* state  = (const float*)d_in[0];
    const float* action = (const float*)d_in[1];
    const float* W1  = (const float*)d_in[2];
    const float* b1  = (const float*)d_in[3];
    const float* g1  = (const float*)d_in[4];
    const float* W2  = (const float*)d_in[5];
    const float* b2  = (const float*)d_in[6];
    const float* g2  = (const float*)d_in[7];
    const float* Wq1 = (const float*)d_in[8];
    const float* bq1 = (const float*)d_in[9];
    const float* l1g = (const float*)d_in[10];
    const float* l1b = (const float*)d_in[11];
    const float* Wq2 = (const float*)d_in[12];
    const float* bq2 = (const float*)d_in[13];
    const float* l2g = (const float*)d_in[14];
    const float* l2b = (const float*)d_in[15];
    const float* Wq3 = (const float*)d_in[16];
    const float* bq3 = (const float*)d_in[17];
    float* out = (float*)d_out;

    int B = in_sizes[0] / 24;
    int grid = B / TM;
    size_t smem = (size_t)SMEM_FLOATS * sizeof(float);
    cudaFuncSetAttribute(cor_critic_fused, cudaFuncAttributeMaxDynamicSharedMemorySize, (int)smem);
    cor_critic_fused<<<grid, NT, smem>>>(state, action, W1, b1, g1, W2, b2, g2,
                                         Wq1, bq1, l1g, l1b, Wq2, bq2, l2g, l2b, Wq3, bq3, out);
}

// round 7
// speedup vs baseline: 2.8773x; 2.8773x over previous
#include <cuda_runtime.h>
#include <cuda_bf16.h>
#include <stdint.h>
#include <math.h>
typedef __nv_bfloat16 bf16;

__device__ __align__(256) bf16 gX1h[(size_t)131072*1024];
__device__ __align__(256) bf16 gX1l[(size_t)131072*1024];
__device__ __align__(256) bf16 gX2h[(size_t)131072*1024];
__device__ __align__(256) bf16 gX2l[(size_t)131072*1024];
__device__ __align__(256) bf16 gW1h[1024*64],   gW1l[1024*64];
__device__ __align__(256) bf16 gW2h[1024*1024], gW2l[1024*1024];
__device__ __align__(256) bf16 gQ1h[256*1024],  gQ1l[256*1024];
__device__ __align__(256) bf16 gQ2h[128*256],   gQ2l[128*256];

__device__ __forceinline__ uint32_t smem_u32(const void* p) {
    uint32_t a; asm("{ .reg .u64 t; cvta.to.shared.u64 t, %1; cvt.u32.u64 %0, t; }" : "=r"(a) : "l"(p));
    return a;
}
__device__ __forceinline__ void cpa16(uint32_t d, const void* s) {
    asm volatile("cp.async.cg.shared.global [%0], [%1], 16;" :: "r"(d), "l"(s));
}
#define CP_COMMIT() asm volatile("cp.async.commit_group;" ::: "memory")
#define CP_WAIT(n)  asm volatile("cp.async.wait_group %0;" :: "n"(n) : "memory")
__device__ __forceinline__ void ldm4(uint32_t* r, uint32_t a) {
    asm volatile("ldmatrix.sync.aligned.m8n8.x4.shared.b16 {%0,%1,%2,%3}, [%4];"
        : "=r"(r[0]), "=r"(r[1]), "=r"(r[2]), "=r"(r[3]) : "r"(a));
}
__device__ __forceinline__ void mma_bf(float* c, const uint32_t* a, const uint32_t* b) {
    asm volatile("mma.sync.aligned.m16n8k16.row.col.f32.bf16.bf16.f32 "
        "{%0,%1,%2,%3}, {%4,%5,%6,%7}, {%8,%9}, {%0,%1,%2,%3};"
        : "+f"(c[0]), "+f"(c[1]), "+f"(c[2]), "+f"(c[3])
        : "r"(a[0]), "r"(a[1]), "r"(a[2]), "r"(a[3]), "r"(b[0]), "r"(b[1]));
}
#define SWZ(x) ((x) ^ (((x) >> 3) & 0x70))
__device__ __forceinline__ uint32_t a_addr(uint32_t base, int r0, int kk, int lane) {
    return base + SWZ((r0 + (lane & 15)) * 128 + kk * 32 + ((lane >> 4) << 4));
}
__device__ __forceinline__ uint32_t b_addr(uint32_t base, int n0, int kk, int lane) {
    return base + SWZ((n0 + (lane & 7) + ((lane >> 4) << 3)) * 128 + kk * 32 + (((lane >> 3) & 1) << 4));
}
template<int R>
__device__ __forceinline__ void cp_tile(uint32_t dsm, const bf16* g, long row0, int stride, int k0, int tid) {
    #pragma unroll
    for (int i = 0; i < R * 8 / 256; ++i) {
        int u = tid + i * 256, r = u >> 3, c = u & 7;
        cpa16(dsm + SWZ(r * 128 + c * 16), g + (row0 + r) * (long)stride + k0 + c * 8);
    }
}
__device__ __forceinline__ void split_bf(float v, bf16& h, bf16& l) {
    h = __float2bfloat16_rn(v);
    l = __float2bfloat16_rn(v - __bfloat162float(h));
}
__device__ __forceinline__ uint32_t pack_bf2(bf16 a, bf16 b) {
    __nv_bfloat162 t; t.x = a; t.y = b; return *reinterpret_cast<uint32_t*>(&t);
}
__device__ __forceinline__ float acc_tanh(float x) {
    float e = expf(2.0f * x);
    return 1.0f - 2.0f / (e + 1.0f);
}
template<int MF>
__device__ __forceinline__ void mma_chunk(float (&c)[MF][8][4], uint32_t bAh, uint32_t bAl,
                                          uint32_t bBh, uint32_t bBl, int m0, int n0, int lane) {
    #pragma unroll
    for (int kk = 0; kk < 4; ++kk) {
        uint32_t Ah[MF][4], Al[MF][4];
        #pragma unroll
        for (int mf = 0; mf < MF; ++mf) {
            ldm4(Ah[mf], a_addr(bAh, m0 + mf * 16, kk, lane));
            ldm4(Al[mf], a_addr(bAl, m0 + mf * 16, kk, lane));
        }
        #pragma unroll
        for (int np = 0; np < 4; ++np) {
            uint32_t Bh[4], Bl[4];
            ldm4(Bh, b_addr(bBh, n0 + np * 16, kk, lane));
            ldm4(Bl, b_addr(bBl, n0 + np * 16, kk, lane));
            #pragma unroll
            for (int mf = 0; mf < MF; ++mf)
                #pragma unroll
                for (int h = 0; h < 2; ++h) {
                    float* cc = c[mf][np * 2 + h];
                    mma_bf(cc, Ah[mf], Bh + h * 2);
                    mma_bf(cc, Al[mf], Bh + h * 2);
                    mma_bf(cc, Ah[mf], Bl + h * 2);
                }
        }
    }
}
__device__ __forceinline__ void epi_store(float (&c)[2][8][4], int m0, int gcol0, int lane,
        long grow0, const float* bias, const float* gate, bf16* gh, bf16* gl) {
    int t4 = lane >> 2, q = lane & 3;
    #pragma unroll
    for (int mf = 0; mf < 2; ++mf)
    #pragma unroll
    for (int s = 0; s < 2; ++s) {
        long gr = (grow0 + m0 + mf * 16 + s * 8 + t4) * 1024;
        #pragma unroll
        for (int nf = 0; nf < 8; ++nf) {
            int col = gcol0 + nf * 8 + q * 2;
            float g = gate[col >> 5];
            float v0 = acc_tanh(c[mf][nf][s * 2]     + bias[col])     * g;
            float v1 = acc_tanh(c[mf][nf][s * 2 + 1] + bias[col + 1]) * g;
            bf16 h0, l0, h1, l1; split_bf(v0, h0, l0); split_bf(v1, h1, l1);
            *(uint32_t*)(gh + gr + col) = pack_bf2(h0, h1);
            *(uint32_t*)(gl + gr + col) = pack_bf2(l0, l1);
        }
    }
}

__global__ void prep(const float* __restrict__ W1, const float* __restrict__ W2,
                     const float* __restrict__ Wq1, const float* __restrict__ Wq2) {
    int gt = blockIdx.x * blockDim.x + threadIdx.x, gs = gridDim.x * blockDim.x;
    bf16 h, l;
    for (int i = gt; i < 1024 * 1024; i += gs) {
        int n = i >> 10, k = i & 1023;
        split_bf(W2[(size_t)(n >> 5) * 32768 + k * 32 + (n & 31)], h, l);
        gW2h[i] = h; gW2l[i] = l;
    }
    for (int i = gt; i < 256 * 1024; i += gs) {
        int qq = i >> 10, n = i & 1023;
        split_bf(Wq1[n * 256 + qq], h, l); gQ1h[i] = h; gQ1l[i] = l;
    }
    for (int i = gt; i < 128 * 256; i += gs) {
        int o = i >> 8, qq = i & 255;
        split_bf(Wq2[qq * 128 + o], h, l); gQ2h[i] = h; gQ2l[i] = l;
    }
    for (int i = gt; i < 1024 * 64; i += gs) {
        int n = i >> 6, d = i & 63;
        float v = (d < 32) ? W1[(n >> 5) * 1024 + d * 32 + (n & 31)] : 0.0f;
        split_bf(v, h, l); gW1h[i] = h; gW1l[i] = l;
    }
}

#define K1_B1S 98304
#define K1_G1S 102400
#define K1_SZ  102528
__global__ __launch_bounds__(256,1) void k1(const float* __restrict__ state, const float* __restrict__ action,
                                            const float* __restrict__ b1, const float* __restrict__ g1) {
    extern __shared__ char smx[];
    const uint32_t sb = smem_u32(smx);
    const int tid = threadIdx.x, lane = tid & 31, wid = tid >> 5;
    const long row0 = (long)blockIdx.x * 128;
    float* b1s = (float*)(smx + K1_B1S);
    float* g1s = (float*)(smx + K1_G1S);
    for (int i = tid; i < 1024; i += 256) b1s[i] = __ldg(b1 + i);
    if (tid < 32) g1s[tid] = 1.f / (1.f + expf(-__ldg(g1 + tid)));
    for (int i = tid; i < 8192; i += 256) ((uint32_t*)smx)[i] = 0;
    __syncthreads();
    for (int i = tid; i < 4096; i += 256) {
        int r = i >> 5, d = i & 31;
        float v = (d < 24) ? __ldg(state + (row0 + r) * 24 + d)
                           : __ldg(action + (row0 + r) * 8 + (d - 24));
        bf16 h, l; split_bf(v, h, l);
        int off = SWZ(r * 128 + d * 2);
        *(bf16*)(smx + off) = h;
        *(bf16*)(smx + 16384 + off) = l;
    }
    __syncthreads();
    const int m0 = (wid & 3) * 32, n0 = (wid >> 2) * 64;
    cp_tile<128>(sb + 32768,         gW1h, 0, 64, 0, tid);
    cp_tile<128>(sb + 32768 + 16384, gW1l, 0, 64, 0, tid);
    CP_COMMIT();
    for (int nt = 0; nt < 8; ++nt) {
        uint32_t bs = sb + 32768 + (nt & 1) * 32768;
        if (nt + 1 < 8) {
            uint32_t bn = sb + 32768 + ((nt + 1) & 1) * 32768;
            cp_tile<128>(bn,         gW1h, (long)(nt + 1) * 128, 64, 0, tid);
            cp_tile<128>(bn + 16384, gW1l, (long)(nt + 1) * 128, 64, 0, tid);
            CP_COMMIT(); CP_WAIT(1);
        } else CP_WAIT(0);
        __syncthreads();
        float c[2][8][4];
        #pragma unroll
        for (int a = 0; a < 2; ++a)
            #pragma unroll
            for (int b = 0; b < 8; ++b)
                #pragma unroll
                for (int e = 0; e < 4; ++e) c[a][b][e] = 0.f;
        mma_chunk<2>(c, sb, sb + 16384, bs, bs + 16384, m0, n0, lane);
        epi_store(c, m0, nt * 128 + n0, lane, row0, b1s, g1s, gX1h, gX1l);
        __syncthreads();
    }
}

#define K2_B2S 131072
#define K2_G2S 135168
#define K2_SZ  135296
__global__ __launch_bounds__(256,1) void k2(const float* __restrict__ b2, const float* __restrict__ g2) {
    extern __shared__ char smx[];
    const uint32_t sb = smem_u32(smx);
    const int tid = threadIdx.x, lane = tid & 31, wid = tid >> 5;
    const long row0 = (long)(blockIdx.x >> 3) * 128;
    const int nt = blockIdx.x & 7;
    float* b2s = (float*)(smx + K2_B2S);
    float* g2s = (float*)(smx + K2_G2S);
    for (int i = tid; i < 1024; i += 256) b2s[i] = __ldg(b2 + i);
    if (tid < 32) g2s[tid] = 1.f / (1.f + expf(-__ldg(g2 + tid)));
    const int m0 = (wid & 3) * 32, n0 = (wid >> 2) * 64;
    auto load = [&](int kc, int s) {
        uint32_t st = sb + s * 65536;
        cp_tile<128>(st,         gX1h, row0, 1024, kc * 64, tid);
        cp_tile<128>(st + 16384, gX1l, row0, 1024, kc * 64, tid);
        cp_tile<128>(st + 32768, gW2h, (long)nt * 128, 1024, kc * 64, tid);
        cp_tile<128>(st + 49152, gW2l, (long)nt * 128, 1024, kc * 64, tid);
        CP_COMMIT();
    };
    load(0, 0);
    float c[2][8][4];
    #pragma unroll
    for (int a = 0; a < 2; ++a)
        #pragma unroll
        for (int b = 0; b < 8; ++b)
            #pragma unroll
            for (int e = 0; e < 4; ++e) c[a][b][e] = 0.f;
    for (int kc = 0; kc < 16; ++kc) {
        if (kc + 1 < 16) { load(kc + 1, (kc + 1) & 1); CP_WAIT(1); } else CP_WAIT(0);
        __syncthreads();
        uint32_t st = sb + (kc & 1) * 65536;
        mma_chunk<2>(c, st, st + 16384, st + 32768, st + 49152, m0, n0, lane);
        __syncthreads();
    }
    epi_store(c, m0, nt * 128 + n0, lane, row0, b2s, g2s, gX2h, gX2l);
}

#define K3_H1H 0
#define K3_H1L 65536
#define K3_WB  131072
#define K3_BQ1 196608
#define K3_L1G 197632
#define K3_L1B 198656
#define K3_BQ2 199680
#define K3_L2G 200192
#define K3_L2B 200704
#define K3_W3  201216
#define K3_PS  201728
#define K3_PQ  203776
#define K3_MU  205824
#define K3_RS  206336
#define K3_PD  206848
#define K3_SZ  207872
__global__ __launch_bounds__(256,1) void k3(const float* __restrict__ bq1, const float* __restrict__ l1g, const float* __restrict__ l1b,
                                            const float* __restrict__ bq2, const float* __restrict__ l2g, const float* __restrict__ l2b,
                                            const float* __restrict__ wq3, const float* __restrict__ bq3, float* __restrict__ out) {
    extern __shared__ char smx[];
    const uint32_t sb = smem_u32(smx);
    const int tid = threadIdx.x, lane = tid & 31, wid = tid >> 5;
    const int t4 = lane >> 2, q = lane & 3;
    const long row0 = (long)blockIdx.x * 128;
    float* bq1s = (float*)(smx + K3_BQ1); float* l1gs = (float*)(smx + K3_L1G);
    float* l1bs = (float*)(smx + K3_L1B); float* bq2s = (float*)(smx + K3_BQ2);
    float* l2gs = (float*)(smx + K3_L2G); float* l2bs = (float*)(smx + K3_L2B);
    float* w3s  = (float*)(smx + K3_W3);
    float* PS = (float*)(smx + K3_PS); float* PQ = (float*)(smx + K3_PQ);
    float* MU = (float*)(smx + K3_MU); float* RS = (float*)(smx + K3_RS);
    float* PD = (float*)(smx + K3_PD);
    bq1s[tid] = __ldg(bq1 + tid); l1gs[tid] = __ldg(l1g + tid); l1bs[tid] = __ldg(l1b + tid);
    if (tid < 128) { bq2s[tid] = __ldg(bq2 + tid); l2gs[tid] = __ldg(l2g + tid);
                     l2bs[tid] = __ldg(l2b + tid); w3s[tid] = __ldg(wq3 + tid); }
    const int m0 = (wid & 1) * 64, n0 = (wid >> 1) * 64, wn = wid >> 1;
    auto load3 = [&](int kc, int s) {
        uint32_t st = sb + s * 98304;
        cp_tile<128>(st,         gX2h, row0, 1024, kc * 64, tid);
        cp_tile<128>(st + 16384, gX2l, row0, 1024, kc * 64, tid);
        cp_tile<256>(st + 32768, gQ1h, 0, 1024, kc * 64, tid);
        cp_tile<256>(st + 65536, gQ1l, 0, 1024, kc * 64, tid);
        CP_COMMIT();
    };
    load3(0, 0);
    float c3[4][8][4];
    #pragma unroll
    for (int a = 0; a < 4; ++a)
        #pragma unroll
        for (int b = 0; b < 8; ++b)
            #pragma unroll
            for (int e = 0; e < 4; ++e) c3[a][b][e] = 0.f;
    for (int kc = 0; kc < 16; ++kc) {
        if (kc + 1 < 16) { load3(kc + 1, (kc + 1) & 1); CP_WAIT(1); } else CP_WAIT(0);
        __syncthreads();
        uint32_t st = sb + (kc & 1) * 98304;
        mma_chunk<4>(c3, st, st + 16384, st + 32768, st + 65536, m0, n0, lane);
        __syncthreads();
    }
    cp_tile<128>(sb + K3_WB,         gQ2h, 0, 256, 0, tid);
    cp_tile<128>(sb + K3_WB + 16384, gQ2l, 0, 256, 0, tid);
    CP_COMMIT();
    #pragma unroll
    for (int mf = 0; mf < 4; ++mf)
        #pragma unroll
        for (int nf = 0; nf < 8; ++nf)
            #pragma unroll
            for (int e = 0; e < 4; ++e)
                c3[mf][nf][e] += bq1s[n0 + nf * 8 + q * 2 + (e & 1)];
    #pragma unroll
    for (int mf = 0; mf < 4; ++mf)
        #pragma unroll
        for (int s = 0; s < 2; ++s) {
            float sm1 = 0.f, sq = 0.f;
            #pragma unroll
            for (int nf = 0; nf < 8; ++nf) {
                float v0 = c3[mf][nf][s*2], v1 = c3[mf][nf][s*2+1];
                sm1 += v0 + v1; sq += v0 * v0 + v1 * v1;
            }
            sm1 += __shfl_xor_sync(~0u, sm1, 1); sm1 += __shfl_xor_sync(~0u, sm1, 2);
            sq  += __shfl_xor_sync(~0u, sq, 1);  sq  += __shfl_xor_sync(~0u, sq, 2);
            if (q == 0) {
                int r = m0 + mf * 16 + s * 8 + t4;
                PS[wn * 128 + r] = sm1; PQ[wn * 128 + r] = sq;
            }
        }
    __syncthreads();
    if (tid < 128) {
        float S  = PS[tid] + PS[128 + tid] + PS[256 + tid] + PS[384 + tid];
        float Q2 = PQ[tid] + PQ[128 + tid] + PQ[256 + tid] + PQ[384 + tid];
        float mu = S * (1.f / 256.f);
        MU[tid] = mu; RS[tid] = rsqrtf(Q2 * (1.f / 256.f) - mu * mu + 1e-5f);
    }
    __syncthreads();
    #pragma unroll
    for (int mf = 0; mf < 4; ++mf)
        #pragma unroll
        for (int s = 0; s < 2; ++s) {
            int r = m0 + mf * 16 + s * 8 + t4;
            float mu = MU[r], rs = RS[r];
            #pragma unroll
            for (int nf = 0; nf < 8; ++nf) {
                int col = n0 + nf * 8 + q * 2;
                float v0 = fmaxf((c3[mf][nf][s*2]   - mu) * rs * l1gs[col]   + l1bs[col],   0.f);
                float v1 = fmaxf((c3[mf][nf][s*2+1] - mu) * rs * l1gs[col+1] + l1bs[col+1], 0.f);
                bf16 h0, l0, h1, l1; split_bf(v0, h0, l0); split_bf(v1, h1, l1);
                int off = ((col >> 6) << 14) + SWZ(r * 128 + (col & 63) * 2);
                *(uint32_t*)(smx + K3_H1H + off) = pack_bf2(h0, h1);
                *(uint32_t*)(smx + K3_H1L + off) = pack_bf2(l0, l1);
            }
        }
    __syncthreads();
    const int m4 = (wid & 3) * 32, n4 = (wid >> 2) * 64, wn4 = wid >> 2;
    float c4[2][8][4];
    #pragma unroll
    for (int a = 0; a < 2; ++a)
        #pragma unroll
        for (int b = 0; b < 8; ++b)
            #pragma unroll
            for (int e = 0; e < 4; ++e) c4[a][b][e] = 0.f;
    for (int qc = 0; qc < 4; ++qc) {
        if (qc + 1 < 4) {
            uint32_t bn = sb + K3_WB + ((qc + 1) & 1) * 32768;
            cp_tile<128>(bn,         gQ2h, 0, 256, (qc + 1) * 64, tid);
            cp_tile<128>(bn + 16384, gQ2l, 0, 256, (qc + 1) * 64, tid);
            CP_COMMIT(); CP_WAIT(1);
        } else CP_WAIT(0);
        __syncthreads();
        uint32_t bs = sb + K3_WB + (qc & 1) * 32768;
        mma_chunk<2>(c4, sb + K3_H1H + qc * 16384, sb + K3_H1L + qc * 16384,
                     bs, bs + 16384, m4, n4, lane);
        __syncthreads();
    }
    #pragma unroll
    for (int mf = 0; mf < 2; ++mf)
        #pragma unroll
        for (int nf = 0; nf < 8; ++nf)
            #pragma unroll
            for (int e = 0; e < 4; ++e)
                c4[mf][nf][e] += bq2s[n4 + nf * 8 + q * 2 + (e & 1)];
    #pragma unroll
    for (int mf = 0; mf < 2; ++mf)
        #pragma unroll
        for (int s = 0; s < 2; ++s) {
            float sm1 = 0.f, sq = 0.f;
            #pragma unroll
            for (int nf = 0; nf < 8; ++nf) {
                float v0 = c4[mf][nf][s*2], v1 = c4[mf][nf][s*2+1];
                sm1 += v0 + v1; sq += v0 * v0 + v1 * v1;
            }
            sm1 += __shfl_xor_sync(~0u, sm1, 1); sm1 += __shfl_xor_sync(~0u, sm1, 2);
            sq  += __shfl_xor_sync(~0u, sq, 1);  sq  += __shfl_xor_sync(~0u, sq, 2);
            if (q == 0) {
                int r = m4 + mf * 16 + s * 8 + t4;
                PS[wn4 * 128 + r] = sm1; PQ[wn4 * 128 + r] = sq;
            }
        }
    __syncthreads();
    if (tid < 128) {
        float S  = PS[tid] + PS[128 + tid];
        float Q2 = PQ[tid] + PQ[128 + tid];
        float mu = S * (1.f / 128.f);
        MU[tid] = mu; RS[tid] = rsqrtf(Q2 * (1.f / 128.f) - mu * mu + 1e-5f);
    }
    __syncthreads();
    #pragma unroll
    for (int mf = 0; mf < 2; ++mf)
        #pragma unroll
        for (int s = 0; s < 2; ++s) {
            int r = m4 + mf * 16 + s * 8 + t4;
            float mu = MU[r], rs = RS[r];
            float d = 0.f;
            #pragma unroll
            for (int nf = 0; nf < 8; ++nf) {
                int col = n4 + nf * 8 + q * 2;
                float v0 = fmaxf((c4[mf][nf][s*2]   - mu) * rs * l2gs[col]   + l2bs[col],   0.f);
                float v1 = fmaxf((c4[mf][nf][s*2+1] - mu) * rs * l2gs[col+1] + l2bs[col+1], 0.f);
                d += v0 * w3s[col] + v1 * w3s[col + 1];
            }
            d += __shfl_xor_sync(~0u, d, 1); d += __shfl_xor_sync(~0u, d, 2);
            if (q == 0) PD[wn4 * 128 + r] = d;
        }
    __syncthreads();
    if (tid < 128) out[row0 + tid] = PD[tid] + PD[128 + tid] + __ldg(bq3);
}

extern "C" void kernel_launch(void* const* d_in, const int* in_sizes, int n_in,
                              void* d_out, int out_size) {
    const float* state  = (const float*)d_in[0];
    const float* action = (const float*)d_in[1];
    const float* W1  = (const float*)d_in[2];
    const float* b1  = (const float*)d_in[3];
    const float* g1  = (const float*)d_in[4];
    const float* W2  = (const float*)d_in[5];
    const float* b2  = (const float*)d_in[6];
    const float* g2  = (const float*)d_in[7];
    const float* Wq1 = (const float*)d_in[8];
    const float* bq1 = (const float*)d_in[9];
    const float* l1g = (const float*)d_in[10];
    const float* l1b = (const float*)d_in[11];
    const float* Wq2 = (const float*)d_in[12];
    const float* bq2 = (const float*)d_in[13];
    const float* l2g = (const float*)d_in[14];
    const float* l2b = (const float*)d_in[15];
    const float* Wq3 = (const float*)d_in[16];
    const float* bq3 = (const float*)d_in[17];
    float* out = (float*)d_out;
    int B = in_sizes[0] / 24;
    int tiles = B / 128;
    cudaFuncSetAttribute(k1, cudaFuncAttributeMaxDynamicSharedMemorySize, K1_SZ);
    cudaFuncSetAttribute(k2, cudaFuncAttributeMaxDynamicSharedMemorySize, K2_SZ);
    cudaFuncSetAttribute(k3, cudaFuncAttributeMaxDynamicSharedMemorySize, K3_SZ);
    prep<<<256, 256>>>(W1, W2, Wq1, Wq2);
    k1<<<tiles, 256, K1_SZ>>>(state, action, b1, g1);
    k2<<<tiles * 8, 256, K2_SZ>>>(b2, g2);
    k3<<<tiles, 256, K3_SZ>>>(bq1, l1g, l1b, bq2, l2g, l2b, Wq3, bq3, out);
}

// round 8
// speedup vs baseline: 4.4091x; 1.5324x over previous
#include <cuda_runtime.h>
#include <cuda_fp16.h>
#include <stdint.h>
#include <math.h>
typedef __half f16;

__device__ __align__(256) f16 gX1h[(size_t)131072*1024];
__device__ __align__(256) f16 gX1l[(size_t)131072*1024];
__device__ __align__(256) f16 gX2h[(size_t)131072*1024];
__device__ __align__(256) f16 gX2l[(size_t)131072*1024];
__device__ __align__(256) f16 gW1[1024*64];
__device__ __align__(256) f16 gW2[1024*1024];
__device__ __align__(256) f16 gQ1[256*1024];
__device__ __align__(256) f16 gQ2[128*256];

__device__ __forceinline__ uint32_t smem_u32(const void* p) {
    uint32_t a; asm("{ .reg .u64 t; cvta.to.shared.u64 t, %1; cvt.u32.u64 %0, t; }" : "=r"(a) : "l"(p));
    return a;
}
__device__ __forceinline__ void cpa16(uint32_t d, const void* s) {
    asm volatile("cp.async.cg.shared.global [%0], [%1], 16;" :: "r"(d), "l"(s));
}
#define CP_COMMIT() asm volatile("cp.async.commit_group;" ::: "memory")
#define CP_WAIT(n)  asm volatile("cp.async.wait_group %0;" :: "n"(n) : "memory")
__device__ __forceinline__ void ldm4(uint32_t* r, uint32_t a) {
    asm volatile("ldmatrix.sync.aligned.m8n8.x4.shared.b16 {%0,%1,%2,%3}, [%4];"
        : "=r"(r[0]), "=r"(r[1]), "=r"(r[2]), "=r"(r[3]) : "r"(a));
}
__device__ __forceinline__ void mma_f16(float* c, const uint32_t* a, const uint32_t* b) {
    asm volatile("mma.sync.aligned.m16n8k16.row.col.f32.f16.f16.f32 "
        "{%0,%1,%2,%3}, {%4,%5,%6,%7}, {%8,%9}, {%0,%1,%2,%3};"
        : "+f"(c[0]), "+f"(c[1]), "+f"(c[2]), "+f"(c[3])
        : "r"(a[0]), "r"(a[1]), "r"(a[2]), "r"(a[3]), "r"(b[0]), "r"(b[1]));
}
#define SWZ(x) ((x) ^ (((x) >> 3) & 0x70))
__device__ __forceinline__ uint32_t a_addr(uint32_t base, int r0, int kk, int lane) {
    return base + SWZ((r0 + (lane & 15)) * 128 + kk * 32 + ((lane >> 4) << 4));
}
__device__ __forceinline__ uint32_t b_addr(uint32_t base, int n0, int kk, int lane) {
    return base + SWZ((n0 + (lane & 7) + ((lane >> 4) << 3)) * 128 + kk * 32 + (((lane >> 3) & 1) << 4));
}
template<int R>
__device__ __forceinline__ void cp_tile(uint32_t dsm, const f16* g, long row0, int stride, int k0, int tid) {
    #pragma unroll
    for (int i = 0; i < R * 8 / 256; ++i) {
        int u = tid + i * 256, r = u >> 3, c = u & 7;
        cpa16(dsm + SWZ(r * 128 + c * 16), g + (row0 + r) * (long)stride + k0 + c * 8);
    }
}
__device__ __forceinline__ void split_h(float v, f16& h, f16& l) {
    h = __float2half_rn(v);
    l = __float2half_rn(v - __half2float(h));
}
__device__ __forceinline__ uint32_t pack_h2(f16 a, f16 b) {
    __half2 t; t.x = a; t.y = b; return *reinterpret_cast<uint32_t*>(&t);
}
__device__ __forceinline__ float acc_tanh(float x) {
    float e = expf(2.0f * x);
    return 1.0f - 2.0f / (e + 1.0f);
}
// 2-pass: D += (Ah + Al) @ Bh  over one K64-slab (KK k-steps of 16)
template<int MF, int KK>
__device__ __forceinline__ void mma_chunk2(float (&c)[MF][8][4], uint32_t bAh, uint32_t bAl,
                                           uint32_t bB, int m0, int n0, int lane) {
    #pragma unroll
    for (int kk = 0; kk < KK; ++kk) {
        uint32_t Ah[MF][4], Al[MF][4];
        #pragma unroll
        for (int mf = 0; mf < MF; ++mf) {
            ldm4(Ah[mf], a_addr(bAh, m0 + mf * 16, kk, lane));
            ldm4(Al[mf], a_addr(bAl, m0 + mf * 16, kk, lane));
        }
        #pragma unroll
        for (int np = 0; np < 4; ++np) {
            uint32_t B[4];
            ldm4(B, b_addr(bB, n0 + np * 16, kk, lane));
            #pragma unroll
            for (int mf = 0; mf < MF; ++mf)
                #pragma unroll
                for (int h = 0; h < 2; ++h) {
                    float* cc = c[mf][np * 2 + h];
                    mma_f16(cc, Ah[mf], B + h * 2);
                    mma_f16(cc, Al[mf], B + h * 2);
                }
        }
    }
}
__device__ __forceinline__ void epi_store(float (&c)[2][8][4], int m0, int gcol0, int lane,
        long grow0, const float* bias, const float* gate, f16* gh, f16* gl) {
    int t4 = lane >> 2, q = lane & 3;
    #pragma unroll
    for (int mf = 0; mf < 2; ++mf)
    #pragma unroll
    for (int s = 0; s < 2; ++s) {
        long gr = (grow0 + m0 + mf * 16 + s * 8 + t4) * 1024;
        #pragma unroll
        for (int nf = 0; nf < 8; ++nf) {
            int col = gcol0 + nf * 8 + q * 2;
            float g = gate[col >> 5];
            float v0 = acc_tanh(c[mf][nf][s * 2]     + bias[col])     * g;
            float v1 = acc_tanh(c[mf][nf][s * 2 + 1] + bias[col + 1]) * g;
            f16 h0, l0, h1, l1; split_h(v0, h0, l0); split_h(v1, h1, l1);
            *(uint32_t*)(gh + gr + col) = pack_h2(h0, h1);
            *(uint32_t*)(gl + gr + col) = pack_h2(l0, l1);
        }
    }
}

__global__ void prep(const float* __restrict__ W1, const float* __restrict__ W2,
                     const float* __restrict__ Wq1, const float* __restrict__ Wq2) {
    int gt = blockIdx.x * blockDim.x + threadIdx.x, gs = gridDim.x * blockDim.x;
    for (int i = gt; i < 1024 * 1024; i += gs) {
        int n = i >> 10, k = i & 1023;
        gW2[i] = __float2half_rn(W2[(size_t)(n >> 5) * 32768 + k * 32 + (n & 31)]);
    }
    for (int i = gt; i < 256 * 1024; i += gs) {
        int qq = i >> 10, n = i & 1023;
        gQ1[i] = __float2half_rn(Wq1[n * 256 + qq]);
    }
    for (int i = gt; i < 128 * 256; i += gs) {
        int o = i >> 8, qq = i & 255;
        gQ2[i] = __float2half_rn(Wq2[qq * 128 + o]);
    }
    for (int i = gt; i < 1024 * 64; i += gs) {
        int n = i >> 6, d = i & 63;
        gW1[i] = __float2half_rn((d < 32) ? W1[(n >> 5) * 1024 + d * 32 + (n & 31)] : 0.0f);
    }
}

#define K1_B1S 65536
#define K1_G1S 69632
#define K1_SZ  69760
__global__ __launch_bounds__(256,2) void k1(const float* __restrict__ state, const float* __restrict__ action,
                                            const float* __restrict__ b1, const float* __restrict__ g1) {
    extern __shared__ char smx[];
    const uint32_t sb = smem_u32(smx);
    const int tid = threadIdx.x, lane = tid & 31, wid = tid >> 5;
    const long row0 = (long)blockIdx.x * 128;
    float* b1s = (float*)(smx + K1_B1S);
    float* g1s = (float*)(smx + K1_G1S);
    for (int i = tid; i < 1024; i += 256) b1s[i] = __ldg(b1 + i);
    if (tid < 32) g1s[tid] = 1.f / (1.f + expf(-__ldg(g1 + tid)));
    for (int i = tid; i < 8192; i += 256) ((uint32_t*)smx)[i] = 0;
    __syncthreads();
    for (int i = tid; i < 4096; i += 256) {
        int r = i >> 5, d = i & 31;
        float v = (d < 24) ? __ldg(state + (row0 + r) * 24 + d)
                           : __ldg(action + (row0 + r) * 8 + (d - 24));
        f16 h, l; split_h(v, h, l);
        int off = SWZ(r * 128 + d * 2);
        *(f16*)(smx + off) = h;
        *(f16*)(smx + 16384 + off) = l;
    }
    __syncthreads();
    const int m0 = (wid & 3) * 32, n0 = (wid >> 2) * 64;
    cp_tile<128>(sb + 32768, gW1, 0, 64, 0, tid);
    CP_COMMIT();
    for (int nt = 0; nt < 8; ++nt) {
        uint32_t bs = sb + 32768 + (nt & 1) * 16384;
        if (nt + 1 < 8) {
            cp_tile<128>(sb + 32768 + ((nt + 1) & 1) * 16384, gW1, (long)(nt + 1) * 128, 64, 0, tid);
            CP_COMMIT(); CP_WAIT(1);
        } else CP_WAIT(0);
        __syncthreads();
        float c[2][8][4];
        #pragma unroll
        for (int a = 0; a < 2; ++a)
            #pragma unroll
            for (int b = 0; b < 8; ++b)
                #pragma unroll
                for (int e = 0; e < 4; ++e) c[a][b][e] = 0.f;
        mma_chunk2<2, 2>(c, sb, sb + 16384, bs, m0, n0, lane);
        epi_store(c, m0, nt * 128 + n0, lane, row0, b1s, g1s, gX1h, gX1l);
        __syncthreads();
    }
}

#define K2_B2S 98304
#define K2_G2S 102400
#define K2_SZ  102528
__global__ __launch_bounds__(256,2) void k2(const float* __restrict__ b2, const float* __restrict__ g2) {
    extern __shared__ char smx[];
    const uint32_t sb = smem_u32(smx);
    const int tid = threadIdx.x, lane = tid & 31, wid = tid >> 5;
    const long row0 = (long)(blockIdx.x >> 3) * 128;
    const int nt = blockIdx.x & 7;
    float* b2s = (float*)(smx + K2_B2S);
    float* g2s = (float*)(smx + K2_G2S);
    for (int i = tid; i < 1024; i += 256) b2s[i] = __ldg(b2 + i);
    if (tid < 32) g2s[tid] = 1.f / (1.f + expf(-__ldg(g2 + tid)));
    const int m0 = (wid & 3) * 32, n0 = (wid >> 2) * 64;
    auto load = [&](int kc, int s) {
        uint32_t st = sb + s * 49152;
        cp_tile<128>(st,         gX1h, row0, 1024, kc * 64, tid);
        cp_tile<128>(st + 16384, gX1l, row0, 1024, kc * 64, tid);
        cp_tile<128>(st + 32768, gW2, (long)nt * 128, 1024, kc * 64, tid);
        CP_COMMIT();
    };
    load(0, 0);
    float c[2][8][4];
    #pragma unroll
    for (int a = 0; a < 2; ++a)
        #pragma unroll
        for (int b = 0; b < 8; ++b)
            #pragma unroll
            for (int e = 0; e < 4; ++e) c[a][b][e] = 0.f;
    for (int kc = 0; kc < 16; ++kc) {
        if (kc + 1 < 16) { load(kc + 1, (kc + 1) & 1); CP_WAIT(1); } else CP_WAIT(0);
        __syncthreads();
        uint32_t st = sb + (kc & 1) * 49152;
        mma_chunk2<2, 4>(c, st, st + 16384, st + 32768, m0, n0, lane);
        __syncthreads();
    }
    epi_store(c, m0, nt * 128 + n0, lane, row0, b2s, g2s, gX2h, gX2l);
}

#define K3_H1H 0
#define K3_H1L 65536
#define K3_WB  131072
#define K3_BQ1 163840
#define K3_L1G 164864
#define K3_L1B 165888
#define K3_BQ2 166912
#define K3_L2G 167424
#define K3_L2B 167936
#define K3_W3  168448
#define K3_PS  168960
#define K3_PQ  171008
#define K3_MU  173056
#define K3_RS  173568
#define K3_PD  174080
#define K3_SZ  176128
__global__ __launch_bounds__(256,1) void k3(const float* __restrict__ bq1, const float* __restrict__ l1g, const float* __restrict__ l1b,
                                            const float* __restrict__ bq2, const float* __restrict__ l2g, const float* __restrict__ l2b,
                                            const float* __restrict__ wq3, const float* __restrict__ bq3, float* __restrict__ out) {
    extern __shared__ char smx[];
    const uint32_t sb = smem_u32(smx);
    const int tid = threadIdx.x, lane = tid & 31, wid = tid >> 5;
    const int t4 = lane >> 2, q = lane & 3;
    const long row0 = (long)blockIdx.x * 128;
    float* bq1s = (float*)(smx + K3_BQ1); float* l1gs = (float*)(smx + K3_L1G);
    float* l1bs = (float*)(smx + K3_L1B); float* bq2s = (float*)(smx + K3_BQ2);
    float* l2gs = (float*)(smx + K3_L2G); float* l2bs = (float*)(smx + K3_L2B);
    float* w3s  = (float*)(smx + K3_W3);
    float* PS = (float*)(smx + K3_PS); float* PQ = (float*)(smx + K3_PQ);
    float* MU = (float*)(smx + K3_MU); float* RS = (float*)(smx + K3_RS);
    float* PD = (float*)(smx + K3_PD);
    bq1s[tid] = __ldg(bq1 + tid); l1gs[tid] = __ldg(l1g + tid); l1bs[tid] = __ldg(l1b + tid);
    if (tid < 128) { bq2s[tid] = __ldg(bq2 + tid); l2gs[tid] = __ldg(l2g + tid);
                     l2bs[tid] = __ldg(l2b + tid); w3s[tid] = __ldg(wq3 + tid); }
    const int m0 = (wid & 1) * 64, n0 = (wid >> 1) * 64, wn = wid >> 1;
    auto load3 = [&](int kc, int s) {
        uint32_t st = sb + s * 65536;
        cp_tile<128>(st,         gX2h, row0, 1024, kc * 64, tid);
        cp_tile<128>(st + 16384, gX2l, row0, 1024, kc * 64, tid);
        cp_tile<256>(st + 32768, gQ1, 0, 1024, kc * 64, tid);
        CP_COMMIT();
    };
    load3(0, 0);
    float c3[4][8][4];
    #pragma unroll
    for (int a = 0; a < 4; ++a)
        #pragma unroll
        for (int b = 0; b < 8; ++b)
            #pragma unroll
            for (int e = 0; e < 4; ++e) c3[a][b][e] = 0.f;
    for (int kc = 0; kc < 16; ++kc) {
        if (kc + 1 < 16) { load3(kc + 1, (kc + 1) & 1); CP_WAIT(1); } else CP_WAIT(0);
        __syncthreads();
        uint32_t st = sb + (kc & 1) * 65536;
        mma_chunk2<4, 4>(c3, st, st + 16384, st + 32768, m0, n0, lane);
        __syncthreads();
    }
    cp_tile<128>(sb + K3_WB, gQ2, 0, 256, 0, tid);
    CP_COMMIT();
    #pragma unroll
    for (int mf = 0; mf < 4; ++mf)
        #pragma unroll
        for (int nf = 0; nf < 8; ++nf)
            #pragma unroll
            for (int e = 0; e < 4; ++e)
                c3[mf][nf][e] += bq1s[n0 + nf * 8 + q * 2 + (e & 1)];
    #pragma unroll
    for (int mf = 0; mf < 4; ++mf)
        #pragma unroll
        for (int s = 0; s < 2; ++s) {
            float sm1 = 0.f, sq = 0.f;
            #pragma unroll
            for (int nf = 0; nf < 8; ++nf) {
                float v0 = c3[mf][nf][s*2], v1 = c3[mf][nf][s*2+1];
                sm1 += v0 + v1; sq += v0 * v0 + v1 * v1;
            }
            sm1 += __shfl_xor_sync(~0u, sm1, 1); sm1 += __shfl_xor_sync(~0u, sm1, 2);
            sq  += __shfl_xor_sync(~0u, sq, 1);  sq  += __shfl_xor_sync(~0u, sq, 2);
            if (q == 0) {
                int r = m0 + mf * 16 + s * 8 + t4;
                PS[wn * 128 + r] = sm1; PQ[wn * 128 + r] = sq;
            }
        }
    __syncthreads();
    if (tid < 128) {
        float S  = PS[tid] + PS[128 + tid] + PS[256 + tid] + PS[384 + tid];
        float Q2 = PQ[tid] + PQ[128 + tid] + PQ[256 + tid] + PQ[384 + tid];
        float mu = S * (1.f / 256.f);
        MU[tid] = mu; RS[tid] = rsqrtf(Q2 * (1.f / 256.f) - mu * mu + 1e-5f);
    }
    __syncthreads();
    #pragma unroll
    for (int mf = 0; mf < 4; ++mf)
        #pragma unroll
        for (int s = 0; s < 2; ++s) {
            int r = m0 + mf * 16 + s * 8 + t4;
            float mu = MU[r], rs = RS[r];
            #pragma unroll
            for (int nf = 0; nf < 8; ++nf) {
                int col = n0 + nf * 8 + q * 2;
                float v0 = fmaxf((c3[mf][nf][s*2]   - mu) * rs * l1gs[col]   + l1bs[col],   0.f);
                float v1 = fmaxf((c3[mf][nf][s*2+1] - mu) * rs * l1gs[col+1] + l1bs[col+1], 0.f);
                f16 h0, l0, h1, l1; split_h(v0, h0, l0); split_h(v1, h1, l1);
                int off = ((col >> 6) << 14) + SWZ(r * 128 + (col & 63) * 2);
                *(uint32_t*)(smx + K3_H1H + off) = pack_h2(h0, h1);
                *(uint32_t*)(smx + K3_H1L + off) = pack_h2(l0, l1);
            }
        }
    __syncthreads();
    const int m4 = (wid & 3) * 32, n4 = (wid >> 2) * 64, wn4 = wid >> 2;
    float c4[2][8][4];
    #pragma unroll
    for (int a = 0; a < 2; ++a)
        #pragma unroll
        for (int b = 0; b < 8; ++b)
            #pragma unroll
            for (int e = 0; e < 4; ++e) c4[a][b][e] = 0.f;
    for (int qc = 0; qc < 4; ++qc) {
        if (qc + 1 < 4) {
            cp_tile<128>(sb + K3_WB + ((qc + 1) & 1) * 16384, gQ2, 0, 256, (qc + 1) * 64, tid);
            CP_COMMIT(); CP_WAIT(1);
        } else CP_WAIT(0);
        __syncthreads();
        uint32_t bs = sb + K3_WB + (qc & 1) * 16384;
        mma_chunk2<2, 4>(c4, sb + K3_H1H + qc * 16384, sb + K3_H1L + qc * 16384,
                         bs, m4, n4, lane);
        __syncthreads();
    }
    #pragma unroll
    for (int mf = 0; mf < 2; ++mf)
        #pragma unroll
        for (int nf = 0; nf < 8; ++nf)
            #pragma unroll
            for (int e = 0; e < 4; ++e)
                c4[mf][nf][e] += bq2s[n4 + nf * 8 + q * 2 + (e & 1)];
    #pragma unroll
    for (int mf = 0; mf < 2; ++mf)
        #pragma unroll
        for (int s = 0; s < 2; ++s) {
            float sm1 = 0.f, sq = 0.f;
            #pragma unroll
            for (int nf = 0; nf < 8; ++nf) {
                float v0 = c4[mf][nf][s*2], v1 = c4[mf][nf][s*2+1];
                sm1 += v0 + v1; sq += v0 * v0 + v1 * v1;
            }
            sm1 += __shfl_xor_sync(~0u, sm1, 1); sm1 += __shfl_xor_sync(~0u, sm1, 2);
            sq  += __shfl_xor_sync(~0u, sq, 1);  sq  += __shfl_xor_sync(~0u, sq, 2);
            if (q == 0) {
                int r = m4 + mf * 16 + s * 8 + t4;
                PS[wn4 * 128 + r] = sm1; PQ[wn4 * 128 + r] = sq;
            }
        }
    __syncthreads();
    if (tid < 128) {
        float S  = PS[tid] + PS[128 + tid];
        float Q2 = PQ[tid] + PQ[128 + tid];
        float mu = S * (1.f / 128.f);
        MU[tid] = mu; RS[tid] = rsqrtf(Q2 * (1.f / 128.f) - mu * mu + 1e-5f);
    }
    __syncthreads();
    #pragma unroll
    for (int mf = 0; mf < 2; ++mf)
        #pragma unroll
        for (int s = 0; s < 2; ++s) {
            int r = m4 + mf * 16 + s * 8 + t4;
            float mu = MU[r], rs = RS[r];
            float d = 0.f;
            #pragma unroll
            for (int nf = 0; nf < 8; ++nf) {
                int col = n4 + nf * 8 + q * 2;
                float v0 = fmaxf((c4[mf][nf][s*2]   - mu) * rs * l2gs[col]   + l2bs[col],   0.f);
                float v1 = fmaxf((c4[mf][nf][s*2+1] - mu) * rs * l2gs[col+1] + l2bs[col+1], 0.f);
                d += v0 * w3s[col] + v1 * w3s[col + 1];
            }
            d += __shfl_xor_sync(~0u, d, 1); d += __shfl_xor_sync(~0u, d, 2);
            if (q == 0) PD[wn4 * 128 + r] = d;
        }
    __syncthreads();
    if (tid < 128) out[row0 + tid] = PD[tid] + PD[128 + tid] + __ldg(bq3);
}

extern "C" void kernel_launch(void* const* d_in, const int* in_sizes, int n_in,
                              void* d_out, int out_size) {
    const float* state  = (const float*)d_in[0];
    const float* action = (const float*)d_in[1];
    const float* W1  = (const float*)d_in[2];
    const float* b1  = (const float*)d_in[3];
    const float* g1  = (const float*)d_in[4];
    const float* W2  = (const float*)d_in[5];
    const float* b2  = (const float*)d_in[6];
    const float* g2  = (const float*)d_in[7];
    const float* Wq1 = (const float*)d_in[8];
    const float* bq1 = (const float*)d_in[9];
    const float* l1g = (const float*)d_in[10];
    const float* l1b = (const float*)d_in[11];
    const float* Wq2 = (const float*)d_in[12];
    const float* bq2 = (const float*)d_in[13];
    const float* l2g = (const float*)d_in[14];
    const float* l2b = (const float*)d_in[15];
    const float* Wq3 = (const float*)d_in[16];
    const float* bq3 = (const float*)d_in[17];
    float* out = (float*)d_out;
    int B = in_sizes[0] / 24;
    int tiles = B / 128;
    cudaFuncSetAttribute(k1, cudaFuncAttributeMaxDynamicSharedMemorySize, K1_SZ);
    cudaFuncSetAttribute(k2, cudaFuncAttributeMaxDynamicSharedMemorySize, K2_SZ);
    cudaFuncSetAttribute(k3, cudaFuncAttributeMaxDynamicSharedMemorySize, K3_SZ);
    prep<<<256, 256>>>(W1, W2, Wq1, Wq2);
    k1<<<tiles, 256, K1_SZ>>>(state, action, b1, g1);
    k2<<<tiles * 8, 256, K2_SZ>>>(b2, g2);
    k3<<<tiles, 256, K3_SZ>>>(bq1, l1g, l1b, bq2, l2g, l2b, Wq3, bq3, out);
}

// round 12
// speedup vs baseline: 7.3218x; 1.6606x over previous
#include <cuda_runtime.h>
#include <cuda_fp16.h>
#include <stdint.h>
#include <math.h>
typedef __half f16;

__device__ __align__(256) f16 gX1[(size_t)131072*1024];
__device__ __align__(256) f16 gX2[(size_t)131072*1024];
__device__ __align__(256) f16 gW1[1024*64];
__device__ __align__(256) f16 gW2[1024*1024];
__device__ __align__(256) f16 gQ1[256*1024];
__device__ __align__(256) f16 gQ2[128*256];

__device__ __forceinline__ uint32_t smem_u32(const void* p) {
    uint32_t a; asm("{ .reg .u64 t; cvta.to.shared.u64 t, %1; cvt.u32.u64 %0, t; }" : "=r"(a) : "l"(p));
    return a;
}
__device__ __forceinline__ void cpa16(uint32_t d, const void* s) {
    asm volatile("cp.async.cg.shared.global [%0], [%1], 16;" :: "r"(d), "l"(s));
}
#define CP_COMMIT() asm volatile("cp.async.commit_group;" ::: "memory")
#define CP_WAIT(n)  asm volatile("cp.async.wait_group %0;" :: "n"(n) : "memory")
__device__ __forceinline__ void ldm4(uint32_t* r, uint32_t a) {
    asm volatile("ldmatrix.sync.aligned.m8n8.x4.shared.b16 {%0,%1,%2,%3}, [%4];"
        : "=r"(r[0]), "=r"(r[1]), "=r"(r[2]), "=r"(r[3]) : "r"(a));
}
__device__ __forceinline__ void mma_f16(float* c, const uint32_t* a, const uint32_t* b) {
    asm volatile("mma.sync.aligned.m16n8k16.row.col.f32.f16.f16.f32 "
        "{%0,%1,%2,%3}, {%4,%5,%6,%7}, {%8,%9}, {%0,%1,%2,%3};"
        : "+f"(c[0]), "+f"(c[1]), "+f"(c[2]), "+f"(c[3])
        : "r"(a[0]), "r"(a[1]), "r"(a[2]), "r"(a[3]), "r"(b[0]), "r"(b[1]));
}
#define SWZ(x) ((x) ^ (((x) >> 3) & 0x70))
__device__ __forceinline__ uint32_t a_addr(uint32_t base, int r0, int kk, int lane) {
    return base + SWZ((r0 + (lane & 15)) * 128 + kk * 32 + ((lane >> 4) << 4));
}
__device__ __forceinline__ uint32_t b_addr(uint32_t base, int n0, int kk, int lane) {
    return base + SWZ((n0 + (lane & 7) + ((lane >> 4) << 3)) * 128 + kk * 32 + (((lane >> 3) & 1) << 4));
}
template<int R>
__device__ __forceinline__ void cp_tile(uint32_t dsm, const f16* g, long row0, int stride, int k0, int tid) {
    #pragma unroll
    for (int i = 0; i < R * 8 / 256; ++i) {
        int u = tid + i * 256, r = u >> 3, c = u & 7;
        cpa16(dsm + SWZ(r * 128 + c * 16), g + (row0 + r) * (long)stride + k0 + c * 8);
    }
}
__device__ __forceinline__ uint32_t pack_h2(f16 a, f16 b) {
    __half2 t; t.x = a; t.y = b; return *reinterpret_cast<uint32_t*>(&t);
}
__device__ __forceinline__ float acc_tanh(float x) {
    float e = expf(2.0f * x);
    return 1.0f - 2.0f / (e + 1.0f);
}
// single-pass fp16 MMA over one K64 slab (KK k-steps of 16)
template<int MF, int KK>
__device__ __forceinline__ void mma_chunk1(float (&c)[MF][8][4], uint32_t bA, uint32_t bB,
                                           int m0, int n0, int lane) {
    #pragma unroll
    for (int kk = 0; kk < KK; ++kk) {
        uint32_t A[MF][4];
        #pragma unroll
        for (int mf = 0; mf < MF; ++mf) ldm4(A[mf], a_addr(bA, m0 + mf * 16, kk, lane));
        #pragma unroll
        for (int np = 0; np < 4; ++np) {
            uint32_t B[4];
            ldm4(B, b_addr(bB, n0 + np * 16, kk, lane));
            #pragma unroll
            for (int mf = 0; mf < MF; ++mf)
                #pragma unroll
                for (int h = 0; h < 2; ++h)
                    mma_f16(c[mf][np * 2 + h], A[mf], B + h * 2);
        }
    }
}
__device__ __forceinline__ void epi_store(float (&c)[2][8][4], int m0, int gcol0, int lane,
        long grow0, const float* bias, const float* gate, f16* gout) {
    int t4 = lane >> 2, q = lane & 3;
    #pragma unroll
    for (int mf = 0; mf < 2; ++mf)
    #pragma unroll
    for (int s = 0; s < 2; ++s) {
        long gr = (grow0 + m0 + mf * 16 + s * 8 + t4) * 1024;
        #pragma unroll
        for (int nf = 0; nf < 8; ++nf) {
            int col = gcol0 + nf * 8 + q * 2;
            float g = gate[col >> 5];
            float v0 = acc_tanh(c[mf][nf][s * 2]     + bias[col])     * g;
            float v1 = acc_tanh(c[mf][nf][s * 2 + 1] + bias[col + 1]) * g;
            *(uint32_t*)(gout + gr + col) = pack_h2(__float2half_rn(v0), __float2half_rn(v1));
        }
    }
}

__global__ void prep(const float* __restrict__ W1, const float* __restrict__ W2,
                     const float* __restrict__ Wq1, const float* __restrict__ Wq2) {
    int gt = blockIdx.x * blockDim.x + threadIdx.x, gs = gridDim.x * blockDim.x;
    for (int i = gt; i < 1024 * 1024; i += gs) {
        int n = i >> 10, k = i & 1023;
        gW2[i] = __float2half_rn(W2[(size_t)(n >> 5) * 32768 + k * 32 + (n & 31)]);
    }
    for (int i = gt; i < 256 * 1024; i += gs) {
        int qq = i >> 10, n = i & 1023;
        gQ1[i] = __float2half_rn(Wq1[n * 256 + qq]);
    }
    for (int i = gt; i < 128 * 256; i += gs) {
        int o = i >> 8, qq = i & 255;
        gQ2[i] = __float2half_rn(Wq2[qq * 128 + o]);
    }
    for (int i = gt; i < 1024 * 64; i += gs) {
        int n = i >> 6, d = i & 63;
        gW1[i] = __float2half_rn((d < 32) ? W1[(n >> 5) * 1024 + d * 32 + (n & 31)] : 0.0f);
    }
}

// ---- k1: X0[128][64] at 0 (16KB), W buf 2x16KB at 16384, b1s 49152, g1s 53248
#define K1_B1S 49152
#define K1_G1S 53248
#define K1_SZ  53376
__global__ __launch_bounds__(256,2) void k1(const float* __restrict__ state, const float* __restrict__ action,
                                            const float* __restrict__ b1, const float* __restrict__ g1) {
    extern __shared__ char smx[];
    const uint32_t sb = smem_u32(smx);
    const int tid = threadIdx.x, lane = tid & 31, wid = tid >> 5;
    const long row0 = (long)blockIdx.x * 128;
    float* b1s = (float*)(smx + K1_B1S);
    float* g1s = (float*)(smx + K1_G1S);
    for (int i = tid; i < 1024; i += 256) b1s[i] = __ldg(b1 + i);
    if (tid < 32) g1s[tid] = 1.f / (1.f + expf(-__ldg(g1 + tid)));
    for (int i = tid; i < 4096; i += 256) ((uint32_t*)smx)[i] = 0;
    __syncthreads();
    for (int i = tid; i < 4096; i += 256) {
        int r = i >> 5, d = i & 31;
        float v = (d < 24) ? __ldg(state + (row0 + r) * 24 + d)
                           : __ldg(action + (row0 + r) * 8 + (d - 24));
        *(f16*)(smx + SWZ(r * 128 + d * 2)) = __float2half_rn(v);
    }
    __syncthreads();
    const int m0 = (wid & 3) * 32, n0 = (wid >> 2) * 64;
    cp_tile<128>(sb + 16384, gW1, 0, 64, 0, tid);
    CP_COMMIT();
    for (int nt = 0; nt < 8; ++nt) {
        uint32_t bs = sb + 16384 + (nt & 1) * 16384;
        if (nt + 1 < 8) {
            cp_tile<128>(sb + 16384 + ((nt + 1) & 1) * 16384, gW1, (long)(nt + 1) * 128, 64, 0, tid);
            CP_COMMIT(); CP_WAIT(1);
        } else CP_WAIT(0);
        __syncthreads();
        float c[2][8][4];
        #pragma unroll
        for (int a = 0; a < 2; ++a)
            #pragma unroll
            for (int b = 0; b < 8; ++b)
                #pragma unroll
                for (int e = 0; e < 4; ++e) c[a][b][e] = 0.f;
        mma_chunk1<2, 2>(c, sb, bs, m0, n0, lane);
        epi_store(c, m0, nt * 128 + n0, lane, row0, b1s, g1s, gX1);
        __syncthreads();
    }
}

// ---- k2: 3 stages x 32KB (A 16KB + B 16KB), b2s 98304, g2s 102400
#define K2_B2S 98304
#define K2_G2S 102400
#define K2_SZ  102528
__global__ __launch_bounds__(256,2) void k2(const float* __restrict__ b2, const float* __restrict__ g2) {
    extern __shared__ char smx[];
    const uint32_t sb = smem_u32(smx);
    const int tid = threadIdx.x, lane = tid & 31, wid = tid >> 5;
    const long row0 = (long)(blockIdx.x >> 3) * 128;
    const int nt = blockIdx.x & 7;
    float* b2s = (float*)(smx + K2_B2S);
    float* g2s = (float*)(smx + K2_G2S);
    for (int i = tid; i < 1024; i += 256) b2s[i] = __ldg(b2 + i);
    if (tid < 32) g2s[tid] = 1.f / (1.f + expf(-__ldg(g2 + tid)));
    const int m0 = (wid & 3) * 32, n0 = (wid >> 2) * 64;
    auto load = [&](int kc) {
        uint32_t st = sb + (kc % 3) * 32768;
        cp_tile<128>(st,         gX1, row0, 1024, kc * 64, tid);
        cp_tile<128>(st + 16384, gW2, (long)nt * 128, 1024, kc * 64, tid);
        CP_COMMIT();
    };
    load(0); load(1);
    float c[2][8][4];
    #pragma unroll
    for (int a = 0; a < 2; ++a)
        #pragma unroll
        for (int b = 0; b < 8; ++b)
            #pragma unroll
            for (int e = 0; e < 4; ++e) c[a][b][e] = 0.f;
    for (int kc = 0; kc < 16; ++kc) {
        if (kc + 2 < 16) { load(kc + 2); CP_WAIT(2); }
        else if (kc + 1 < 16) CP_WAIT(1);
        else CP_WAIT(0);
        __syncthreads();
        uint32_t st = sb + (kc % 3) * 32768;
        mma_chunk1<2, 4>(c, st, st + 16384, m0, n0, lane);
        __syncthreads();
    }
    epi_store(c, m0, nt * 128 + n0, lane, row0, b2s, g2s, gX2);
}

// ---- k3: 3 stages x 48KB (A 16KB + Q1 32KB) at 0..147456; H1 64KB at 147456;
//      Q2 double buffer reuses stage area; params at 212992+
#define K3_H1  147456
#define K3_BQ1 212992
#define K3_L1G 214016
#define K3_L1B 215040
#define K3_BQ2 216064
#define K3_L2G 216576
#define K3_L2B 217088
#define K3_W3  217600
#define K3_PS  218112
#define K3_PQ  220160
#define K3_MU  222208
#define K3_RS  222720
#define K3_PD  223232
#define K3_SZ  225280
__global__ __launch_bounds__(256,1) void k3(const float* __restrict__ bq1, const float* __restrict__ l1g, const float* __restrict__ l1b,
                                            const float* __restrict__ bq2, const float* __restrict__ l2g, const float* __restrict__ l2b,
                                            const float* __restrict__ wq3, const float* __restrict__ bq3, float* __restrict__ out) {
    extern __shared__ char smx[];
    const uint32_t sb = smem_u32(smx);
    const int tid = threadIdx.x, lane = tid & 31, wid = tid >> 5;
    const int t4 = lane >> 2, q = lane & 3;
    const long row0 = (long)blockIdx.x * 128;
    float* bq1s = (float*)(smx + K3_BQ1); float* l1gs = (float*)(smx + K3_L1G);
    float* l1bs = (float*)(smx + K3_L1B); float* bq2s = (float*)(smx + K3_BQ2);
    float* l2gs = (float*)(smx + K3_L2G); float* l2bs = (float*)(smx + K3_L2B);
    float* w3s  = (float*)(smx + K3_W3);
    float* PS = (float*)(smx + K3_PS); float* PQ = (float*)(smx + K3_PQ);
    float* MU = (float*)(smx + K3_MU); float* RS = (float*)(smx + K3_RS);
    float* PD = (float*)(smx + K3_PD);
    bq1s[tid] = __ldg(bq1 + tid); l1gs[tid] = __ldg(l1g + tid); l1bs[tid] = __ldg(l1b + tid);
    if (tid < 128) { bq2s[tid] = __ldg(bq2 + tid); l2gs[tid] = __ldg(l2g + tid);
                     l2bs[tid] = __ldg(l2b + tid); w3s[tid] = __ldg(wq3 + tid); }
    const int m0 = (wid & 1) * 64, n0 = (wid >> 1) * 64, wn = wid >> 1;
    auto load3 = [&](int kc) {
        uint32_t st = sb + (kc % 3) * 49152;
        cp_tile<128>(st,         gX2, row0, 1024, kc * 64, tid);
        cp_tile<256>(st + 16384, gQ1, 0, 1024, kc * 64, tid);
        CP_COMMIT();
    };
    load3(0); load3(1);
    float c3[4][8][4];
    #pragma unroll
    for (int a = 0; a < 4; ++a)
        #pragma unroll
        for (int b = 0; b < 8; ++b)
            #pragma unroll
            for (int e = 0; e < 4; ++e) c3[a][b][e] = 0.f;
    for (int kc = 0; kc < 16; ++kc) {
        if (kc + 2 < 16) { load3(kc + 2); CP_WAIT(2); }
        else if (kc + 1 < 16) CP_WAIT(1);
        else CP_WAIT(0);
        __syncthreads();
        uint32_t st = sb + (kc % 3) * 49152;
        mma_chunk1<4, 4>(c3, st, st + 16384, m0, n0, lane);
        __syncthreads();
    }
    cp_tile<128>(sb, gQ2, 0, 256, 0, tid);
    CP_COMMIT();
    #pragma unroll
    for (int mf = 0; mf < 4; ++mf)
        #pragma unroll
        for (int nf = 0; nf < 8; ++nf)
            #pragma unroll
            for (int e = 0; e < 4; ++e)
                c3[mf][nf][e] += bq1s[n0 + nf * 8 + q * 2 + (e & 1)];
    #pragma unroll
    for (int mf = 0; mf < 4; ++mf)
        #pragma unroll
        for (int s = 0; s < 2; ++s) {
            float sm1 = 0.f, sq = 0.f;
            #pragma unroll
            for (int nf = 0; nf < 8; ++nf) {
                float v0 = c3[mf][nf][s*2], v1 = c3[mf][nf][s*2+1];
                sm1 += v0 + v1; sq += v0 * v0 + v1 * v1;
            }
            sm1 += __shfl_xor_sync(~0u, sm1, 1); sm1 += __shfl_xor_sync(~0u, sm1, 2);
            sq  += __shfl_xor_sync(~0u, sq, 1);  sq  += __shfl_xor_sync(~0u, sq, 2);
            if (q == 0) {
                int r = m0 + mf * 16 + s * 8 + t4;
                PS[wn * 128 + r] = sm1; PQ[wn * 128 + r] = sq;
            }
        }
    __syncthreads();
    if (tid < 128) {
        float S  = PS[tid] + PS[128 + tid] + PS[256 + tid] + PS[384 + tid];
        float Q2 = PQ[tid] + PQ[128 + tid] + PQ[256 + tid] + PQ[384 + tid];
        float mu = S * (1.f / 256.f);
        MU[tid] = mu; RS[tid] = rsqrtf(Q2 * (1.f / 256.f) - mu * mu + 1e-5f);
    }
    __syncthreads();
    #pragma unroll
    for (int mf = 0; mf < 4; ++mf)
        #pragma unroll
        for (int s = 0; s < 2; ++s) {
            int r = m0 + mf * 16 + s * 8 + t4;
            float mu = MU[r], rs = RS[r];
            #pragma unroll
            for (int nf = 0; nf < 8; ++nf) {
                int col = n0 + nf * 8 + q * 2;
                float v0 = fmaxf((c3[mf][nf][s*2]   - mu) * rs * l1gs[col]   + l1bs[col],   0.f);
                float v1 = fmaxf((c3[mf][nf][s*2+1] - mu) * rs * l1gs[col+1] + l1bs[col+1], 0.f);
                int off = K3_H1 + ((col >> 6) << 14) + SWZ(r * 128 + (col & 63) * 2);
                *(uint32_t*)(smx + off) = pack_h2(__float2half_rn(v0), __float2half_rn(v1));
            }
        }
    __syncthreads();
    const int m4 = (wid & 3) * 32, n4 = (wid >> 2) * 64, wn4 = wid >> 2;
    float c4[2][8][4];
    #pragma unroll
    for (int a = 0; a < 2; ++a)
        #pragma unroll
        for (int b = 0; b < 8; ++b)
            #pragma unroll
            for (int e = 0; e < 4; ++e) c4[a][b][e] = 0.f;
    for (int qc = 0; qc < 4; ++qc) {
        if (qc + 1 < 4) {
            cp_tile<128>(sb + ((qc + 1) & 1) * 16384, gQ2, 0, 256, (qc + 1) * 64, tid);
            CP_COMMIT(); CP_WAIT(1);
        } else CP_WAIT(0);
        __syncthreads();
        mma_chunk1<2, 4>(c4, sb + K3_H1 + qc * 16384, sb + (qc & 1) * 16384, m4, n4, lane);
        __syncthreads();
    }
    #pragma unroll
    for (int mf = 0; mf < 2; ++mf)
        #pragma unroll
        for (int nf = 0; nf < 8; ++nf)
            #pragma unroll
            for (int e = 0; e < 4; ++e)
                c4[mf][nf][e] += bq2s[n4 + nf * 8 + q * 2 + (e & 1)];
    #pragma unroll
    for (int mf = 0; mf < 2; ++mf)
        #pragma unroll
        for (int s = 0; s < 2; ++s) {
            float sm1 = 0.f, sq = 0.f;
            #pragma unroll
            for (int nf = 0; nf < 8; ++nf) {
                float v0 = c4[mf][nf][s*2], v1 = c4[mf][nf][s*2+1];
                sm1 += v0 + v1; sq += v0 * v0 + v1 * v1;
            }
            sm1 += __shfl_xor_sync(~0u, sm1, 1); sm1 += __shfl_xor_sync(~0u, sm1, 2);
            sq  += __shfl_xor_sync(~0u, sq, 1);  sq  += __shfl_xor_sync(~0u, sq, 2);
            if (q == 0) {
                int r = m4 + mf * 16 + s * 8 + t4;
                PS[wn4 * 128 + r] = sm1; PQ[wn4 * 128 + r] = sq;
            }
        }
    __syncthreads();
    if (tid < 128) {
        float S  = PS[tid] + PS[128 + tid];
        float Q2 = PQ[tid] + PQ[128 + tid];
        float mu = S * (1.f / 128.f);
        MU[tid] = mu; RS[tid] = rsqrtf(Q2 * (1.f / 128.f) - mu * mu + 1e-5f);
    }
    __syncthreads();
    #pragma unroll
    for (int mf = 0; mf < 2; ++mf)
        #pragma unroll
        for (int s = 0; s < 2; ++s) {
            int r = m4 + mf * 16 + s * 8 + t4;
            float mu = MU[r], rs = RS[r];
            float d = 0.f;
            #pragma unroll
            for (int nf = 0; nf < 8; ++nf) {
                int col = n4 + nf * 8 + q * 2;
                float v0 = fmaxf((c4[mf][nf][s*2]   - mu) * rs * l2gs[col]   + l2bs[col],   0.f);
                float v1 = fmaxf((c4[mf][nf][s*2+1] - mu) * rs * l2gs[col+1] + l2bs[col+1], 0.f);
                d += v0 * w3s[col] + v1 * w3s[col + 1];
            }
            d += __shfl_xor_sync(~0u, d, 1); d += __shfl_xor_sync(~0u, d, 2);
            if (q == 0) PD[wn4 * 128 + r] = d;
        }
    __syncthreads();
    if (tid < 128) out[row0 + tid] = PD[tid] + PD[128 + tid] + __ldg(bq3);
}

extern "C" void kernel_launch(void* const* d_in, const int* in_sizes, int n_in,
                              void* d_out, int out_size) {
    const float* state  = (const float*)d_in[0];
    const float* action = (const float*)d_in[1];
    const float* W1  = (const float*)d_in[2];
    const float* b1  = (const float*)d_in[3];
    const float* g1  = (const float*)d_in[4];
    const float* W2  = (const float*)d_in[5];
    const float* b2  = (const float*)d_in[6];
    const float* g2  = (const float*)d_in[7];
    const float* Wq1 = (const float*)d_in[8];
    const float* bq1 = (const float*)d_in[9];
    const float* l1g = (const float*)d_in[10];
    const float* l1b = (const float*)d_in[11];
    const float* Wq2 = (const float*)d_in[12];
    const float* bq2 = (const float*)d_in[13];
    const float* l2g = (const float*)d_in[14];
    const float* l2b = (const float*)d_in[15];
    const float* Wq3 = (const float*)d_in[16];
    const float* bq3 = (const float*)d_in[17];
    float* out = (float*)d_out;
    int B = in_sizes[0] / 24;
    int tiles = B / 128;
    cudaFuncSetAttribute(k1, cudaFuncAttributeMaxDynamicSharedMemorySize, K1_SZ);
    cudaFuncSetAttribute(k2, cudaFuncAttributeMaxDynamicSharedMemorySize, K2_SZ);
    cudaFuncSetAttribute(k3, cudaFuncAttributeMaxDynamicSharedMemorySize, K3_SZ);
    prep<<<256, 256>>>(W1, W2, Wq1, Wq2);
    k1<<<tiles, 256, K1_SZ>>>(state, action, b1, g1);
    k2<<<tiles * 8, 256, K2_SZ>>>(b2, g2);
    k3<<<tiles, 256, K3_SZ>>>(bq1, l1g, l1b, bq2, l2g, l2b, Wq3, bq3, out);
}